// round 15
// baseline (speedup 1.0000x reference)
#include <cuda_runtime.h>
#include <cuda_fp16.h>

#define NN 100000
#define NP (NN + 128)
#define EE 600000
#define HD 128
#define KSB 144          // SMEM row stride bytes for 64 fp16 cols (+8 elem pad)
#define BSE 72
#define NTILE 782        // ceil(NN/128)
#define GRID 304
#define IMGH (2 * 128 * BSE)   // halves per B image (2 chunks x 128 rows x 72)

typedef unsigned long long u64;
typedef unsigned int u32;

// ---------------- scratch (device globals) ----------------
__device__ __align__(16) __half g_xh[(size_t)NP * HD];
__device__ __align__(16) __half g_h[(size_t)NP * HD];
__device__ __align__(16) __half g_zl[(size_t)NP * HD];
__device__ __align__(16) __half g_zr[(size_t)NP * HD];
__device__ int   g_cnt[NN];
__device__ int   g_rowstart[NN + 1];
__device__ int   g_cursor[NN];
__device__ int   g_csrc[EE];
// 5 B images (N=128 each): L1Wl, L1Wr, L2Wl, L2Wr, L3[Wl|Wr]
__device__ __align__(16) __half g_bimg[5 * IMGH];
__device__ float g_ss[3 * 256];   // per layer: s[128], sh[128]

// ---------------- PTX helpers ----------------
__device__ __forceinline__ u32 smem_u32(const void* p) {
    u32 a;
    asm("{ .reg .u64 t; cvta.to.shared.u64 t, %1; cvt.u32.u64 %0, t; }" : "=r"(a) : "l"(p));
    return a;
}
__device__ __forceinline__ void ldsm4(u32* r, u32 addr) {
    asm volatile("ldmatrix.sync.aligned.m8n8.x4.shared.b16 {%0,%1,%2,%3}, [%4];"
                 : "=r"(r[0]), "=r"(r[1]), "=r"(r[2]), "=r"(r[3]) : "r"(addr));
}
__device__ __forceinline__ void mma16816(float* c, const u32* a, u32 b0, u32 b1) {
    asm volatile("mma.sync.aligned.m16n8k16.row.col.f32.f16.f16.f32 "
                 "{%0,%1,%2,%3}, {%4,%5,%6,%7}, {%8,%9}, {%0,%1,%2,%3};"
                 : "+f"(c[0]), "+f"(c[1]), "+f"(c[2]), "+f"(c[3])
                 : "r"(a[0]), "r"(a[1]), "r"(a[2]), "r"(a[3]), "r"(b0), "r"(b1));
}
__device__ __forceinline__ void cpasync16(u32 smem_addr, const void* gptr) {
    asm volatile("cp.async.cg.shared.global [%0], [%1], 16;"
                 :: "r"(smem_addr), "l"(gptr) : "memory");
}
#define CP_COMMIT() asm volatile("cp.async.commit_group;" ::: "memory")

// ================= CSR build =================
__global__ void k_hist(const int* __restrict__ dst) {
    int e = blockIdx.x * blockDim.x + threadIdx.x;
    if (e < EE) atomicAdd(&g_cnt[dst[e]], 1);
}

__global__ void k_scan() {   // single block, 1024 threads; restores g_cnt=0
    __shared__ int sh[1024];
    const int tid = threadIdx.x;
    const int CH = (NN + 1023) / 1024;
    int base = tid * CH;
    int end  = min(base + CH, NN);
    int s = 0;
    for (int i = base; i < end; i++) s += g_cnt[i];
    sh[tid] = s;
    __syncthreads();
    for (int off = 1; off < 1024; off <<= 1) {
        int v = (tid >= off) ? sh[tid - off] : 0;
        __syncthreads();
        sh[tid] += v;
        __syncthreads();
    }
    int run = sh[tid] - s;
    for (int i = base; i < end; i++) {
        int c = g_cnt[i];
        g_rowstart[i] = run;
        g_cursor[i]   = run;
        g_cnt[i]      = 0;
        run += c;
    }
    if (tid == 0) g_rowstart[NN] = EE;
}

__global__ void k_slot(const int* __restrict__ src, const int* __restrict__ dst) {
    int e = blockIdx.x * blockDim.x + threadIdx.x;
    if (e < EE) {
        int d = dst[e];
        int slot = atomicAdd(&g_cursor[d], 1);
        g_csrc[slot] = src[e];
    }
}

// ================= x -> fp16 copy =================
__global__ void k_xhalf(const float* __restrict__ x) {
    int t = blockIdx.x * blockDim.x + threadIdx.x;
    if (t >= NN * HD / 8) return;
    float4 v0 = __ldg((const float4*)x + t * 2);
    float4 v1 = __ldg((const float4*)x + t * 2 + 1);
    __half2 h0 = __floats2half2_rn(v0.x, v0.y);
    __half2 h1 = __floats2half2_rn(v0.z, v0.w);
    __half2 h2 = __floats2half2_rn(v1.x, v1.y);
    __half2 h3 = __floats2half2_rn(v1.z, v1.w);
    uint4 p;
    p.x = *(u32*)&h0; p.y = *(u32*)&h1; p.z = *(u32*)&h2; p.w = *(u32*)&h3;
    ((uint4*)g_xh)[t] = p;
}

// ================= weight prepack + BN constants (one launch) =================
// Images: 0=L1Wl, 1=L1Wr, 2=L2Wl, 3=L2Wr, 4=L3[Wl|Wr]. B[n][k]=W[k][n], padded rows.
__global__ void k_bpackall(const float* __restrict__ Wl1, const float* __restrict__ Wr1,
                           const float* __restrict__ Wl2, const float* __restrict__ Wr2,
                           const float* __restrict__ Wl3, const float* __restrict__ Wr3,
                           const float* __restrict__ bl1, const float* __restrict__ g1,
                           const float* __restrict__ be1, const float* __restrict__ rm1,
                           const float* __restrict__ rv1,
                           const float* __restrict__ bl2, const float* __restrict__ g2,
                           const float* __restrict__ be2, const float* __restrict__ rm2,
                           const float* __restrict__ rv2,
                           const float* __restrict__ bl3) {
    int t = blockIdx.x * blockDim.x + threadIdx.x;
    const int WTOT = 5 * 2 * 128 * 64;
    if (t < WTOT) {
        int im = t / (2 * 128 * 64);
        int rem = t % (2 * 128 * 64);
        int chunk = rem / (128 * 64);
        int n = (rem % (128 * 64)) / 64;
        int kk = rem % 64;
        int gk = chunk * 64 + kk;
        float v;
        if (im == 0)      v = __ldg(Wl1 + gk * 128 + n);
        else if (im == 1) v = __ldg(Wr1 + gk * 128 + n);
        else if (im == 2) v = __ldg(Wl2 + gk * 128 + n);
        else if (im == 3) v = __ldg(Wr2 + gk * 128 + n);
        else              v = (n < 64) ? __ldg(Wl3 + gk * 64 + n)
                                       : __ldg(Wr3 + gk * 64 + (n - 64));
        g_bimg[im * IMGH + chunk * 128 * BSE + n * BSE + kk] = __float2half_rn(v);
    } else if (t < WTOT + 3 * 128) {
        int idx = t - WTOT;
        int layer = idx / 128, c = idx % 128;
        float s, sh;
        if (layer == 0) {
            s = __ldg(&g1[c]) * rsqrtf(__ldg(&rv1[c]) + 1e-5f);
            sh = (__ldg(&bl1[c]) - __ldg(&rm1[c])) * s + __ldg(&be1[c]);
        } else if (layer == 1) {
            s = __ldg(&g2[c]) * rsqrtf(__ldg(&rv2[c]) + 1e-5f);
            sh = (__ldg(&bl2[c]) - __ldg(&rm2[c])) * s + __ldg(&be2[c]);
        } else {
            s = (c < 64) ? 1.0f : 0.0f;
            sh = (c < 64) ? __ldg(&bl3[c]) : 0.0f;
        }
        g_ss[layer * 256 + c] = s;
        g_ss[layer * 256 + 128 + c] = sh;
    }
}

// ================= dense GEMM: Z = X @ W (M=100k, N=128, K=128) ===============
// GRID blocks grid-stride over 782 M-tiles of 128. 512 thr = 16 warps 4x4,
// warp tile 32x32 (acc 32 regs). K as 2 chunks of 64; A double-buffered
// cp.async across tiles; B (both chunks) SMEM-resident, staged once.
__global__ __launch_bounds__(512, 2)
void k_gemm(const __half* __restrict__ xin, __half* __restrict__ zout,
            const __half* __restrict__ bimg)
{
    extern __shared__ char smem[];
    constexpr int ABYT = 128 * KSB;          // 18432
    constexpr int BBYT = 128 * KSB;
    constexpr int SM_B = 2 * ABYT;

    const int tid  = threadIdx.x;
    const int wid  = tid >> 5;
    const int lane = tid & 31;
    const int wr   = (wid >> 2) * 32;
    const int wc   = (wid & 3) * 32;
    const int bid  = blockIdx.x;
    const u32 sb   = smem_u32(smem);

    // stage both B chunk images once (raw contiguous copy)
    {
        const char* bsrc = (const char*)bimg;
        for (int i = tid; i < 2 * BBYT / 16; i += 512)
            cpasync16(sb + SM_B + i * 16, bsrc + i * 16);
    }

    const int ntiles = (NTILE - 1 - bid) / GRID + 1;
    const int Q = ntiles * 2;

    auto stageq = [&](int qq) {
        size_t nb2 = (size_t)(bid + (qq >> 1) * GRID) * 128;
        const int co = (qq & 1) * 128;   // byte offset in 256B row
        const u32 adst = sb + (qq & 1) * ABYT;
        for (int idx = tid; idx < 1024; idx += 512) {
            int r = idx >> 3, i = idx & 7;
            cpasync16(adst + r * KSB + i * 16,
                      (const char*)(xin + (nb2 + r) * HD) + co + i * 16);
        }
    };

    stageq(0);
    CP_COMMIT();

    const u32 aOff = (u32)((wr + (lane & 15)) * KSB + (lane >> 4) * 16);
    const u32 bOff = (u32)((wc + (lane & 15)) * KSB + (lane >> 4) * 16);
    const int cb = (lane & 3) * 2;

    float acc[2][4][4];
    #pragma unroll
    for (int m = 0; m < 2; m++)
        #pragma unroll
        for (int j = 0; j < 4; j++) {
            acc[m][j][0] = 0.f; acc[m][j][1] = 0.f;
            acc[m][j][2] = 0.f; acc[m][j][3] = 0.f;
        }

    for (int q = 0; q < Q; q++) {
        if (q + 1 < Q) {
            stageq(q + 1);
            CP_COMMIT();
            asm volatile("cp.async.wait_group 1;" ::: "memory");
        } else {
            asm volatile("cp.async.wait_group 0;" ::: "memory");
        }
        __syncthreads();

        const u32 abuf = sb + (q & 1) * ABYT + aOff;
        const u32 bbuf = sb + SM_B + (q & 1) * BBYT + bOff;
        #pragma unroll
        for (int k16 = 0; k16 < 4; k16++) {
            u32 a0[4], a1[4];
            ldsm4(a0, abuf + k16 * 32);
            ldsm4(a1, abuf + 16 * KSB + k16 * 32);
            #pragma unroll
            for (int jp = 0; jp < 2; jp++) {
                u32 bb[4];
                ldsm4(bb, bbuf + jp * 16 * KSB + k16 * 32);
                mma16816(acc[0][2 * jp],     a0, bb[0], bb[2]);
                mma16816(acc[1][2 * jp],     a1, bb[0], bb[2]);
                mma16816(acc[0][2 * jp + 1], a0, bb[1], bb[3]);
                mma16816(acc[1][2 * jp + 1], a1, bb[1], bb[3]);
            }
        }

        if (q & 1) {
            int nb = (bid + (q >> 1) * GRID) * 128;
            // store full tile, THEN reset (reset must not clobber acc[1] before m=1 stores)
            #pragma unroll
            for (int m = 0; m < 2; m++) {
                #pragma unroll
                for (int j = 0; j < 4; j++) {
                    int c = wc + j * 8 + cb;
                    #pragma unroll
                    for (int hh = 0; hh < 2; hh++) {
                        int n = nb + wr + m * 16 + (lane >> 2) + hh * 8;
                        if (n >= NN) continue;
                        __half2 hv = __floats2half2_rn(acc[m][j][hh * 2], acc[m][j][hh * 2 + 1]);
                        *(u32*)(zout + (size_t)n * HD + c) = *(u32*)&hv;
                    }
                }
            }
            #pragma unroll
            for (int m = 0; m < 2; m++)
                #pragma unroll
                for (int j = 0; j < 4; j++) {
                    acc[m][j][0] = 0.f; acc[m][j][1] = 0.f;
                    acc[m][j][2] = 0.f; acc[m][j][3] = 0.f;
                }
        }
        __syncthreads();
    }
}

// ================= fused gather + epilogue ====================================
// out[n] = epi( mean_{src in N(n)} Zl[src] + Zr[n] ).  16 threads per node
// (2 nodes/warp). Zl/Zr rows have stride 128 halves. V = N_/16 halves/thread.
template<int N_, bool LAST>
__global__ void k_gath(const __half* __restrict__ Zl, const __half* __restrict__ Zr,
                       void* __restrict__ hout, const float* __restrict__ ss)
{
    constexpr int V = N_ / 16;               // 8 or 4
    int t = blockIdx.x * blockDim.x + threadIdx.x;
    int node = t >> 4;
    if (node >= NN) return;
    int sl = t & 15;

    int b = __ldg(&g_rowstart[node]), e = __ldg(&g_rowstart[node + 1]);
    float acc[V], acc2[V];
    #pragma unroll
    for (int i = 0; i < V; i++) { acc[i] = 0.f; acc2[i] = 0.f; }

    const size_t lo = (size_t)sl * V;
    int j = b;
    for (; j + 1 < e; j += 2) {
        int s0 = __ldg(&g_csrc[j]);
        int s1 = __ldg(&g_csrc[j + 1]);
        const __half* p0 = Zl + (size_t)s0 * HD + lo;
        const __half* p1 = Zl + (size_t)s1 * HD + lo;
        if (V == 8) {
            uint4 u0 = __ldg((const uint4*)p0);
            uint4 u1 = __ldg((const uint4*)p1);
            const u32* w0 = &u0.x; const u32* w1 = &u1.x;
            #pragma unroll
            for (int k = 0; k < 4; k++) {
                float2 f0 = __half22float2(*(const __half2*)&w0[k]);
                float2 f1 = __half22float2(*(const __half2*)&w1[k]);
                acc[2 * k] += f0.x;  acc[2 * k + 1] += f0.y;
                acc2[2 * k] += f1.x; acc2[2 * k + 1] += f1.y;
            }
        } else {
            uint2 u0 = __ldg((const uint2*)p0);
            uint2 u1 = __ldg((const uint2*)p1);
            const u32* w0 = &u0.x; const u32* w1 = &u1.x;
            #pragma unroll
            for (int k = 0; k < 2; k++) {
                float2 f0 = __half22float2(*(const __half2*)&w0[k]);
                float2 f1 = __half22float2(*(const __half2*)&w1[k]);
                acc[2 * k] += f0.x;  acc[2 * k + 1] += f0.y;
                acc2[2 * k] += f1.x; acc2[2 * k + 1] += f1.y;
            }
        }
    }
    if (j < e) {
        int s0 = __ldg(&g_csrc[j]);
        const __half* p0 = Zl + (size_t)s0 * HD + lo;
        if (V == 8) {
            uint4 u0 = __ldg((const uint4*)p0);
            const u32* w0 = &u0.x;
            #pragma unroll
            for (int k = 0; k < 4; k++) {
                float2 f0 = __half22float2(*(const __half2*)&w0[k]);
                acc[2 * k] += f0.x; acc[2 * k + 1] += f0.y;
            }
        } else {
            uint2 u0 = __ldg((const uint2*)p0);
            const u32* w0 = &u0.x;
            #pragma unroll
            for (int k = 0; k < 2; k++) {
                float2 f0 = __half22float2(*(const __half2*)&w0[k]);
                acc[2 * k] += f0.x; acc[2 * k + 1] += f0.y;
            }
        }
    }

    float inv = 1.0f / fmaxf((float)(e - b), 1.0f);
    float y[V];
    {
        const __half* pz = Zr + (size_t)node * HD + lo;
        if (V == 8) {
            uint4 uz = __ldg((const uint4*)pz);
            const u32* wz = &uz.x;
            #pragma unroll
            for (int k = 0; k < 4; k++) {
                float2 fz = __half22float2(*(const __half2*)&wz[k]);
                y[2 * k]     = (acc[2 * k] + acc2[2 * k]) * inv + fz.x;
                y[2 * k + 1] = (acc[2 * k + 1] + acc2[2 * k + 1]) * inv + fz.y;
            }
        } else {
            uint2 uz = __ldg((const uint2*)pz);
            const u32* wz = &uz.x;
            #pragma unroll
            for (int k = 0; k < 2; k++) {
                float2 fz = __half22float2(*(const __half2*)&wz[k]);
                y[2 * k]     = (acc[2 * k] + acc2[2 * k]) * inv + fz.x;
                y[2 * k + 1] = (acc[2 * k + 1] + acc2[2 * k + 1]) * inv + fz.y;
            }
        }
    }

    int col0 = sl * V;
    if (!LAST) {
        u32 ov[V / 2];
        #pragma unroll
        for (int i = 0; i < V; i++) {
            float s  = __ldg(ss + col0 + i);
            float sh = __ldg(ss + 128 + col0 + i);
            y[i] = fmaxf(y[i] * s + sh, 0.f);
        }
        #pragma unroll
        for (int k = 0; k < V / 2; k++) {
            __half2 hv = __floats2half2_rn(y[2 * k], y[2 * k + 1]);
            ov[k] = *(u32*)&hv;
        }
        uint4 o; o.x = ov[0]; o.y = ov[1]; o.z = ov[2]; o.w = ov[3];
        *(uint4*)((__half*)hout + (size_t)node * N_ + col0) = o;
    } else {
        float4 o;
        o.x = y[0] + __ldg(ss + 128 + col0 + 0);
        o.y = y[1] + __ldg(ss + 128 + col0 + 1);
        o.z = y[2] + __ldg(ss + 128 + col0 + 2);
        o.w = y[3] + __ldg(ss + 128 + col0 + 3);
        *(float4*)((float*)hout + (size_t)node * N_ + col0) = o;
    }
}

// ================= launch =================
extern "C" void kernel_launch(void* const* d_in, const int* in_sizes, int n_in,
                              void* d_out, int out_size) {
    const float* x    = (const float*)d_in[0];
    const int*   ei   = (const int*)  d_in[1];
    const float* Wl1  = (const float*)d_in[2];
    const float* bl1  = (const float*)d_in[3];
    const float* Wr1  = (const float*)d_in[4];
    const float* g1   = (const float*)d_in[5];
    const float* be1  = (const float*)d_in[6];
    const float* rm1  = (const float*)d_in[7];
    const float* rv1  = (const float*)d_in[8];
    const float* Wl2  = (const float*)d_in[9];
    const float* bl2  = (const float*)d_in[10];
    const float* Wr2  = (const float*)d_in[11];
    const float* g2   = (const float*)d_in[12];
    const float* be2  = (const float*)d_in[13];
    const float* rm2  = (const float*)d_in[14];
    const float* rv2  = (const float*)d_in[15];
    const float* Wl3  = (const float*)d_in[16];
    const float* bl3  = (const float*)d_in[17];
    const float* Wr3  = (const float*)d_in[18];
    const int* src = ei;
    const int* dst = ei + EE;
    float* out = (float*)d_out;

    __half *xh_p, *h_p, *zl_p, *zr_p, *b_p;
    float* ss_p;
    cudaGetSymbolAddress((void**)&xh_p, g_xh);
    cudaGetSymbolAddress((void**)&h_p,  g_h);
    cudaGetSymbolAddress((void**)&zl_p, g_zl);
    cudaGetSymbolAddress((void**)&zr_p, g_zr);
    cudaGetSymbolAddress((void**)&b_p,  g_bimg);
    cudaGetSymbolAddress((void**)&ss_p, g_ss);

    constexpr int SMEMG = 4 * 128 * KSB;   // 73728
    cudaFuncSetAttribute(k_gemm, cudaFuncAttributeMaxDynamicSharedMemorySize, SMEMG);

    const int EB = (EE + 255) / 256;
    const int GATHB = (NN * 16 + 255) / 256;   // 6250
    const int PACKT = 5 * 2 * 128 * 64 + 3 * 128;

    // CSR build + fp16 convert + weight/BN pack
    k_hist<<<EB, 256>>>(dst);
    k_scan<<<1, 1024>>>();
    k_slot<<<EB, 256>>>(src, dst);
    k_xhalf<<<(NN * HD / 8 + 255) / 256, 256>>>(x);
    k_bpackall<<<(PACKT + 255) / 256, 256>>>(Wl1, Wr1, Wl2, Wr2, Wl3, Wr3,
                                             bl1, g1, be1, rm1, rv1,
                                             bl2, g2, be2, rm2, rv2, bl3);

    // layer 1
    k_gemm<<<GRID, 512, SMEMG>>>(xh_p, zl_p, b_p + 0 * IMGH);
    k_gemm<<<GRID, 512, SMEMG>>>(xh_p, zr_p, b_p + 1 * IMGH);
    k_gath<HD, false><<<GATHB, 256>>>(zl_p, zr_p, h_p, ss_p + 0 * 256);

    // layer 2
    k_gemm<<<GRID, 512, SMEMG>>>(h_p, zl_p, b_p + 2 * IMGH);
    k_gemm<<<GRID, 512, SMEMG>>>(h_p, zr_p, b_p + 3 * IMGH);
    k_gath<HD, false><<<GATHB, 256>>>(zl_p, zr_p, h_p, ss_p + 1 * 256);

    // layer 3: single GEMM with [Wl3|Wr3] concat -> zl cols 0..63 / 64..127
    k_gemm<<<GRID, 512, SMEMG>>>(h_p, zl_p, b_p + 4 * IMGH);
    k_gath<64, true><<<GATHB, 256>>>(zl_p, zl_p + 64, out, ss_p + 2 * 256);
}

// round 16
// speedup vs baseline: 1.0962x; 1.0962x over previous
#include <cuda_runtime.h>
#include <cuda_fp16.h>

#define NN 100000
#define NP (NN + 128)    // padded rows so node-kernel cp.async never reads OOB
#define EE 600000
#define HD 128
#define OD3 64
#define KSB 144          // SMEM row stride bytes for 64 fp16 cols (+8 elem pad)
#define BSE 72           // same in elements
#define XN (NN * HD / 8) // uint4 elements in xhalf convert

typedef unsigned long long u64;
typedef unsigned int u32;

// ---------------- scratch (device globals) ----------------
__device__ __align__(16) __half g_xh[(size_t)NP * HD];    // fp16 copy of x
__device__ __align__(16) __half g_agg[(size_t)NP * HD];   // fp16 mean-agg
__device__ __align__(16) __half g_h[(size_t)NP * HD];     // fp16 hidden acts
__device__ int   g_cnt[NN];          // zero at rest; re-zeroed by k_scan
__device__ int   g_rowstart[NN + 1];
__device__ int   g_cursor[NN];
__device__ int   g_csrc[EE];
// fp16 weight images: [layer][chunk 0..3][n*BSE + kk]; B = W^T.
// chunks 0,1 = Wl k[0:64),[64:128); chunks 2,3 = Wr.
__device__ __align__(16) __half g_bimg[3][4][HD * BSE];

// ---------------- PTX helpers ----------------
__device__ __forceinline__ u32 smem_u32(const void* p) {
    u32 a;
    asm("{ .reg .u64 t; cvta.to.shared.u64 t, %1; cvt.u32.u64 %0, t; }" : "=r"(a) : "l"(p));
    return a;
}
__device__ __forceinline__ void ldsm4(u32* r, u32 addr) {
    asm volatile("ldmatrix.sync.aligned.m8n8.x4.shared.b16 {%0,%1,%2,%3}, [%4];"
                 : "=r"(r[0]), "=r"(r[1]), "=r"(r[2]), "=r"(r[3]) : "r"(addr));
}
__device__ __forceinline__ void ldsm2(u32* r, u32 addr) {
    asm volatile("ldmatrix.sync.aligned.m8n8.x2.shared.b16 {%0,%1}, [%2];"
                 : "=r"(r[0]), "=r"(r[1]) : "r"(addr));
}
__device__ __forceinline__ void mma16816(float* c, const u32* a, const u32* b) {
    asm volatile("mma.sync.aligned.m16n8k16.row.col.f32.f16.f16.f32 "
                 "{%0,%1,%2,%3}, {%4,%5,%6,%7}, {%8,%9}, {%0,%1,%2,%3};"
                 : "+f"(c[0]), "+f"(c[1]), "+f"(c[2]), "+f"(c[3])
                 : "r"(a[0]), "r"(a[1]), "r"(a[2]), "r"(a[3]), "r"(b[0]), "r"(b[1]));
}
__device__ __forceinline__ void cpasync16(u32 smem_addr, const void* gptr) {
    asm volatile("cp.async.cg.shared.global [%0], [%1], 16;"
                 :: "r"(smem_addr), "l"(gptr) : "memory");
}
#define CP_COMMIT() asm volatile("cp.async.commit_group;" ::: "memory")

// ================= fused: edge histogram + x->fp16 convert =================
__global__ void k_pre1(const int* __restrict__ dst, const float* __restrict__ x) {
    int t = blockIdx.x * blockDim.x + threadIdx.x;
    if (t < EE) {
        atomicAdd(&g_cnt[__ldg(&dst[t])], 1);
    } else {
        int i = t - EE;
        if (i < XN) {
            float4 v0 = __ldg((const float4*)x + i * 2);
            float4 v1 = __ldg((const float4*)x + i * 2 + 1);
            __half2 h0 = __floats2half2_rn(v0.x, v0.y);
            __half2 h1 = __floats2half2_rn(v0.z, v0.w);
            __half2 h2 = __floats2half2_rn(v1.x, v1.y);
            __half2 h3 = __floats2half2_rn(v1.z, v1.w);
            uint4 p;
            p.x = *(u32*)&h0; p.y = *(u32*)&h1; p.z = *(u32*)&h2; p.w = *(u32*)&h3;
            ((uint4*)g_xh)[i] = p;
        }
    }
}

// ================= scan (single block, 1024 threads; restores g_cnt=0) =======
__global__ void k_scan() {
    __shared__ int sh[1024];
    const int tid = threadIdx.x;
    const int CH = (NN + 1023) / 1024;
    int base = tid * CH;
    int end  = min(base + CH, NN);
    int s = 0;
    for (int i = base; i < end; i++) s += g_cnt[i];
    sh[tid] = s;
    __syncthreads();
    for (int off = 1; off < 1024; off <<= 1) {
        int v = (tid >= off) ? sh[tid - off] : 0;
        __syncthreads();
        sh[tid] += v;
        __syncthreads();
    }
    int run = sh[tid] - s;
    for (int i = base; i < end; i++) {
        int c = g_cnt[i];
        g_rowstart[i] = run;
        g_cursor[i]   = run;
        g_cnt[i]      = 0;
        run += c;
    }
    if (tid == 0) g_rowstart[NN] = EE;
}

// ================= fused: CSR slot fill + weight prepack ====================
__global__ void k_pre2(const int* __restrict__ src, const int* __restrict__ dst,
                       const float* __restrict__ Wl1, const float* __restrict__ Wr1,
                       const float* __restrict__ Wl2, const float* __restrict__ Wr2,
                       const float* __restrict__ Wl3, const float* __restrict__ Wr3) {
    int t = blockIdx.x * blockDim.x + threadIdx.x;
    if (t < EE) {
        int d = __ldg(&dst[t]);
        int slot = atomicAdd(&g_cursor[d], 1);
        g_csrc[slot] = __ldg(&src[t]);
        return;
    }
    int w = t - EE;
    if (w >= 3 * 4 * 64 * HD) return;
    int layer = w / (4 * 64 * HD);
    int rem   = w % (4 * 64 * HD);
    int chunk = rem / (64 * HD);
    int rem2  = rem % (64 * HD);
    int kk = rem2 / HD, n = rem2 % HD;
    int N_ = (layer == 2) ? OD3 : HD;
    if (n >= N_) return;
    const float* W;
    if (layer == 0)      W = (chunk < 2) ? Wl1 : Wr1;
    else if (layer == 1) W = (chunk < 2) ? Wl2 : Wr2;
    else                 W = (chunk < 2) ? Wl3 : Wr3;
    int gk = (chunk & 1) * 64 + kk;
    g_bimg[layer][chunk][n * BSE + kk] = __float2half_rn(__ldg(W + gk * N_ + n));
}

// ================= mean aggregation: warp per node, fp16 rows =================
__global__ void k_gather(const __half* __restrict__ xin) {
    int w = (blockIdx.x * blockDim.x + threadIdx.x) >> 5;
    if (w >= NN) return;
    int lane = threadIdx.x & 31;
    int b = g_rowstart[w], e2 = g_rowstart[w + 1];
    float a0 = 0.f, a1 = 0.f, a2 = 0.f, a3 = 0.f;
    float b0 = 0.f, b1 = 0.f, b2 = 0.f, b3 = 0.f;
    int j = b;
    for (; j + 1 < e2; j += 2) {
        int s0 = __ldg(&g_csrc[j]);
        int s1 = __ldg(&g_csrc[j + 1]);
        uint2 p0 = __ldg((const uint2*)(xin + (size_t)s0 * HD) + lane);
        uint2 p1 = __ldg((const uint2*)(xin + (size_t)s1 * HD) + lane);
        float2 f0 = __half22float2(*(__half2*)&p0.x);
        float2 f1 = __half22float2(*(__half2*)&p0.y);
        float2 g0 = __half22float2(*(__half2*)&p1.x);
        float2 g1 = __half22float2(*(__half2*)&p1.y);
        a0 += f0.x; a1 += f0.y; a2 += f1.x; a3 += f1.y;
        b0 += g0.x; b1 += g0.y; b2 += g1.x; b3 += g1.y;
    }
    if (j < e2) {
        int s0 = __ldg(&g_csrc[j]);
        uint2 p0 = __ldg((const uint2*)(xin + (size_t)s0 * HD) + lane);
        float2 f0 = __half22float2(*(__half2*)&p0.x);
        float2 f1 = __half22float2(*(__half2*)&p0.y);
        a0 += f0.x; a1 += f0.y; a2 += f1.x; a3 += f1.y;
    }
    float inv = 1.0f / fmaxf((float)(e2 - b), 1.0f);
    __half2 o0 = __floats2half2_rn((a0 + b0) * inv, (a1 + b1) * inv);
    __half2 o1 = __floats2half2_rn((a2 + b2) * inv, (a3 + b3) * inv);
    uint2 o;
    o.x = *(u32*)&o0; o.y = *(u32*)&o1;
    ((uint2*)(g_agg + (size_t)w * HD))[lane] = o;
}

// ================= pipelined node GEMM: fp16 A and B, cp.async everything =====
// Block: 128 nodes, 256 threads = 8 warps (4 row x 2 col groups), warp tile 32 x N_/2.
// K = 256 as 4 chunks of 64 (agg,agg,x,x); A and B double-buffered cp.async.
// LAST=false: fp16 out (g_h) with BN+ReLU; LAST=true: fp32 out, bias only.
template<int N_, bool LAST>
__global__ __launch_bounds__(256, 2)
void k_node(const __half* __restrict__ xh, void* __restrict__ hout, int layer,
            const float* __restrict__ bl, const float* __restrict__ g,
            const float* __restrict__ be, const float* __restrict__ rm,
            const float* __restrict__ rv)
{
    extern __shared__ char smem[];
    constexpr int ABYT = 128 * KSB;          // one A buffer
    constexpr int BBYT = N_ * KSB;           // one B buffer
    constexpr int SM_B0 = 2 * ABYT;
    constexpr int SM_SC = 2 * ABYT + 2 * BBYT;
    constexpr int SM_SH = SM_SC + 512;
    constexpr int NJ = N_ / 16;

    const int tid  = threadIdx.x;
    const int wid  = tid >> 5;
    const int lane = tid & 31;
    const int wr   = (wid >> 1) * 32;
    const int wc   = (wid & 1) * (N_ / 2);
    const int nb   = blockIdx.x * 128;
    const u32 sb   = smem_u32(smem);

    // BN scale/shift (bias folded)
    if (tid < N_) {
        float s, sh;
        if (!LAST) {
            float sc_ = __ldg(&g[tid]) * rsqrtf(__ldg(&rv[tid]) + 1e-5f);
            s  = sc_;
            sh = (__ldg(&bl[tid]) - __ldg(&rm[tid])) * sc_ + __ldg(&be[tid]);
        } else {
            s  = 1.0f;
            sh = __ldg(&bl[tid]);
        }
        *(float*)(smem + SM_SC + tid * 4) = s;
        *(float*)(smem + SM_SH + tid * 4) = sh;
    }

    // ---- async stage of one chunk (A: 1024 x 16B, B: BBYT/16 x 16B) ----
    auto stage = [&](int cc, int buf) {
        const __half* asrc = (cc < 2) ? g_agg : xh;
        const int co = (cc & 1) * 128;       // byte offset within 256B row
        const u32 adst = sb + buf * ABYT;
        for (int idx = tid; idx < 1024; idx += 256) {
            int r = idx >> 3, i = idx & 7;
            cpasync16(adst + r * KSB + i * 16,
                      (const char*)(asrc + (size_t)(nb + r) * HD) + co + i * 16);
        }
        const char* bsrc = (const char*)&g_bimg[layer][cc][0];
        const u32 bdst = sb + SM_B0 + buf * BBYT;
        for (int i = tid; i < BBYT / 16; i += 256)
            cpasync16(bdst + i * 16, bsrc + i * 16);
    };

    stage(0, 0);
    CP_COMMIT();

    const u32 aOff = (u32)((wr + (lane & 15)) * KSB + (lane >> 4) * 16);
    const u32 bOff = (u32)((wc + (lane & 7)) * KSB + ((lane >> 3) & 1) * 16);

    float acc[2][NJ][4];
    #pragma unroll
    for (int m = 0; m < 2; m++)
        #pragma unroll
        for (int j = 0; j < NJ; j++) {
            acc[m][j][0] = 0.f; acc[m][j][1] = 0.f;
            acc[m][j][2] = 0.f; acc[m][j][3] = 0.f;
        }

    #pragma unroll
    for (int chunk = 0; chunk < 4; chunk++) {
        if (chunk < 3) {
            stage(chunk + 1, (chunk + 1) & 1);
            CP_COMMIT();
            asm volatile("cp.async.wait_group 1;" ::: "memory");
        } else {
            asm volatile("cp.async.wait_group 0;" ::: "memory");
        }
        __syncthreads();   // chunk's buffers visible to all threads

        const u32 abuf = sb + (chunk & 1) * ABYT + aOff;
        const u32 bbuf = sb + SM_B0 + (chunk & 1) * BBYT + bOff;
        #pragma unroll
        for (int k16 = 0; k16 < 4; k16++) {
            u32 a0[4], a1[4];
            ldsm4(a0, abuf + k16 * 32);
            ldsm4(a1, abuf + 16 * KSB + k16 * 32);
            #pragma unroll
            for (int j = 0; j < NJ; j++) {
                u32 bh[2];
                ldsm2(bh, bbuf + j * 8 * KSB + k16 * 32);
                mma16816(acc[0][j], a0, bh);
                mma16816(acc[1][j], a1, bh);
            }
        }
        __syncthreads();   // done reading before next-next stage overwrites
    }

    // ---- epilogue ----
    const int cb = (lane & 3) * 2;
    #pragma unroll
    for (int m = 0; m < 2; m++) {
        int n0 = nb + wr + m * 16 + (lane >> 2);
        int n1 = n0 + 8;
        #pragma unroll
        for (int j = 0; j < NJ; j++) {
            int c = wc + j * 8 + cb;
            float s0 = *(const float*)(smem + SM_SC + c * 4);
            float s1 = *(const float*)(smem + SM_SC + (c + 1) * 4);
            float h0 = *(const float*)(smem + SM_SH + c * 4);
            float h1 = *(const float*)(smem + SM_SH + (c + 1) * 4);
            #pragma unroll
            for (int hh = 0; hh < 2; hh++) {
                int n = (hh == 0) ? n0 : n1;
                if (n >= NN) continue;
                float vx = acc[m][j][hh * 2 + 0] * s0 + h0;
                float vy = acc[m][j][hh * 2 + 1] * s1 + h1;
                if (!LAST) {
                    vx = fmaxf(vx, 0.f);
                    vy = fmaxf(vy, 0.f);
                    __half2 hv = __floats2half2_rn(vx, vy);
                    *(u32*)((__half*)hout + (size_t)n * N_ + c) = *(u32*)&hv;
                } else {
                    float2 o; o.x = vx; o.y = vy;
                    *(float2*)((float*)hout + (size_t)n * N_ + c) = o;
                }
            }
        }
    }
}

// ================= launch =================
extern "C" void kernel_launch(void* const* d_in, const int* in_sizes, int n_in,
                              void* d_out, int out_size) {
    const float* x    = (const float*)d_in[0];
    const int*   ei   = (const int*)  d_in[1];
    const float* Wl1  = (const float*)d_in[2];
    const float* bl1  = (const float*)d_in[3];
    const float* Wr1  = (const float*)d_in[4];
    const float* g1   = (const float*)d_in[5];
    const float* be1  = (const float*)d_in[6];
    const float* rm1  = (const float*)d_in[7];
    const float* rv1  = (const float*)d_in[8];
    const float* Wl2  = (const float*)d_in[9];
    const float* bl2  = (const float*)d_in[10];
    const float* Wr2  = (const float*)d_in[11];
    const float* g2   = (const float*)d_in[12];
    const float* be2  = (const float*)d_in[13];
    const float* rm2  = (const float*)d_in[14];
    const float* rv2  = (const float*)d_in[15];
    const float* Wl3  = (const float*)d_in[16];
    const float* bl3  = (const float*)d_in[17];
    const float* Wr3  = (const float*)d_in[18];
    const int* src = ei;
    const int* dst = ei + EE;
    float* out = (float*)d_out;

    __half *xh_p, *h_p;
    cudaGetSymbolAddress((void**)&xh_p, g_xh);
    cudaGetSymbolAddress((void**)&h_p,  g_h);

    constexpr int SMEM12 = 2 * 128 * KSB + 2 * HD  * KSB + 1024;   // 74752
    constexpr int SMEM3  = 2 * 128 * KSB + 2 * OD3 * KSB + 1024;   // 56320
    cudaFuncSetAttribute(k_node<HD, false>, cudaFuncAttributeMaxDynamicSharedMemorySize, SMEM12);
    cudaFuncSetAttribute(k_node<OD3, true>, cudaFuncAttributeMaxDynamicSharedMemorySize, SMEM3);

    const int GB = (NN * 32 + 255) / 256;
    const int NB = (NN + 127) / 128;   // 782
    const int P1 = (EE + XN + 255) / 256;
    const int P2 = (EE + 3 * 4 * 64 * HD + 255) / 256;

    // fused pre-processing: (hist + xhalf) -> scan -> (slot + bpack)
    k_pre1<<<P1, 256>>>(dst, x);
    k_scan<<<1, 1024>>>();
    k_pre2<<<P2, 256>>>(src, dst, Wl1, Wr1, Wl2, Wr2, Wl3, Wr3);

    // layer 1
    k_gather<<<GB, 256>>>(xh_p);
    k_node<HD, false><<<NB, 256, SMEM12>>>(xh_p, h_p, 0, bl1, g1, be1, rm1, rv1);

    // layer 2 (in place safe: node reads only its own rows of g_h / g_agg)
    k_gather<<<GB, 256>>>(h_p);
    k_node<HD, false><<<NB, 256, SMEM12>>>(h_p, h_p, 1, bl2, g2, be2, rm2, rv2);

    // layer 3
    k_gather<<<GB, 256>>>(h_p);
    k_node<OD3, true><<<NB, 256, SMEM3>>>(h_p, out, 2, bl3, bl3, bl3, bl3, bl3);
}

// round 17
// speedup vs baseline: 1.1097x; 1.0123x over previous
#include <cuda_runtime.h>
#include <cuda_fp16.h>

#define NN 100000
#define NP (NN + 128)    // padded rows so node-kernel cp.async never reads OOB
#define EE 600000
#define HD 128
#define OD3 64
#define KSB 144          // SMEM row stride bytes for 64 fp16 cols (+8 elem pad)
#define BSE 72           // same in elements
#define XN (NN * HD / 8) // uint4 elements in xhalf convert

typedef unsigned long long u64;
typedef unsigned int u32;

// ---------------- scratch (device globals) ----------------
__device__ __align__(16) __half g_xh[(size_t)NP * HD];    // fp16 copy of x
__device__ __align__(16) __half g_agg[(size_t)NP * HD];   // fp16 mean-agg
__device__ __align__(16) __half g_h[(size_t)NP * HD];     // fp16 hidden acts
__device__ int   g_cnt[NN];          // zero at rest; re-zeroed by k_scan
__device__ int   g_rowstart[NN + 1];
__device__ int   g_cursor[NN];
__device__ int   g_csrc[EE];
// fp16 weight images: [layer][chunk 0..3][n*BSE + kk]; B = W^T.
// chunks 0,1 = Wl k[0:64),[64:128); chunks 2,3 = Wr.
__device__ __align__(16) __half g_bimg[3][4][HD * BSE];

// ---------------- PTX helpers ----------------
__device__ __forceinline__ u32 smem_u32(const void* p) {
    u32 a;
    asm("{ .reg .u64 t; cvta.to.shared.u64 t, %1; cvt.u32.u64 %0, t; }" : "=r"(a) : "l"(p));
    return a;
}
__device__ __forceinline__ void ldsm4(u32* r, u32 addr) {
    asm volatile("ldmatrix.sync.aligned.m8n8.x4.shared.b16 {%0,%1,%2,%3}, [%4];"
                 : "=r"(r[0]), "=r"(r[1]), "=r"(r[2]), "=r"(r[3]) : "r"(addr));
}
__device__ __forceinline__ void ldsm2(u32* r, u32 addr) {
    asm volatile("ldmatrix.sync.aligned.m8n8.x2.shared.b16 {%0,%1}, [%2];"
                 : "=r"(r[0]), "=r"(r[1]) : "r"(addr));
}
__device__ __forceinline__ void mma16816(float* c, const u32* a, const u32* b) {
    asm volatile("mma.sync.aligned.m16n8k16.row.col.f32.f16.f16.f32 "
                 "{%0,%1,%2,%3}, {%4,%5,%6,%7}, {%8,%9}, {%0,%1,%2,%3};"
                 : "+f"(c[0]), "+f"(c[1]), "+f"(c[2]), "+f"(c[3])
                 : "r"(a[0]), "r"(a[1]), "r"(a[2]), "r"(a[3]), "r"(b[0]), "r"(b[1]));
}
__device__ __forceinline__ void cpasync16(u32 smem_addr, const void* gptr) {
    asm volatile("cp.async.cg.shared.global [%0], [%1], 16;"
                 :: "r"(smem_addr), "l"(gptr) : "memory");
}
#define CP_COMMIT() asm volatile("cp.async.commit_group;" ::: "memory")

// ================= fused: edge histogram + x->fp16 convert =================
__global__ void k_pre1(const int* __restrict__ dst, const float* __restrict__ x) {
    int t = blockIdx.x * blockDim.x + threadIdx.x;
    if (t < EE) {
        atomicAdd(&g_cnt[__ldg(&dst[t])], 1);
    } else {
        int i = t - EE;
        if (i < XN) {
            float4 v0 = __ldg((const float4*)x + i * 2);
            float4 v1 = __ldg((const float4*)x + i * 2 + 1);
            __half2 h0 = __floats2half2_rn(v0.x, v0.y);
            __half2 h1 = __floats2half2_rn(v0.z, v0.w);
            __half2 h2 = __floats2half2_rn(v1.x, v1.y);
            __half2 h3 = __floats2half2_rn(v1.z, v1.w);
            uint4 p;
            p.x = *(u32*)&h0; p.y = *(u32*)&h1; p.z = *(u32*)&h2; p.w = *(u32*)&h3;
            ((uint4*)g_xh)[i] = p;
        }
    }
}

// ================= scan (single block, 1024 threads; restores g_cnt=0) =======
__global__ void k_scan() {
    __shared__ int sh[1024];
    const int tid = threadIdx.x;
    const int CH = (NN + 1023) / 1024;
    int base = tid * CH;
    int end  = min(base + CH, NN);
    int s = 0;
    for (int i = base; i < end; i++) s += g_cnt[i];
    sh[tid] = s;
    __syncthreads();
    for (int off = 1; off < 1024; off <<= 1) {
        int v = (tid >= off) ? sh[tid - off] : 0;
        __syncthreads();
        sh[tid] += v;
        __syncthreads();
    }
    int run = sh[tid] - s;
    for (int i = base; i < end; i++) {
        int c = g_cnt[i];
        g_rowstart[i] = run;
        g_cursor[i]   = run;
        g_cnt[i]      = 0;
        run += c;
    }
    if (tid == 0) g_rowstart[NN] = EE;
}

// ================= fused: CSR slot fill + weight prepack ====================
__global__ void k_pre2(const int* __restrict__ src, const int* __restrict__ dst,
                       const float* __restrict__ Wl1, const float* __restrict__ Wr1,
                       const float* __restrict__ Wl2, const float* __restrict__ Wr2,
                       const float* __restrict__ Wl3, const float* __restrict__ Wr3) {
    int t = blockIdx.x * blockDim.x + threadIdx.x;
    if (t < EE) {
        int d = __ldg(&dst[t]);
        int slot = atomicAdd(&g_cursor[d], 1);
        g_csrc[slot] = __ldg(&src[t]);
        return;
    }
    int w = t - EE;
    if (w >= 3 * 4 * 64 * HD) return;
    int layer = w / (4 * 64 * HD);
    int rem   = w % (4 * 64 * HD);
    int chunk = rem / (64 * HD);
    int rem2  = rem % (64 * HD);
    int kk = rem2 / HD, n = rem2 % HD;
    int N_ = (layer == 2) ? OD3 : HD;
    if (n >= N_) return;
    const float* W;
    if (layer == 0)      W = (chunk < 2) ? Wl1 : Wr1;
    else if (layer == 1) W = (chunk < 2) ? Wl2 : Wr2;
    else                 W = (chunk < 2) ? Wl3 : Wr3;
    int gk = (chunk & 1) * 64 + kk;
    g_bimg[layer][chunk][n * BSE + kk] = __float2half_rn(__ldg(W + gk * N_ + n));
}

// ================= mean aggregation: 16 lanes/node, pairwise HADD2 ===========
// 2 nodes per warp; each lane covers 8 halves (uint4). Pairs of edges are
// pre-summed in fp16 (HADD2, exact-ish: inputs already fp16), then converted
// and accumulated in fp32. 4-edge unrolled body = 4 LDGs in flight.
__global__ void k_gather(const __half* __restrict__ xin) {
    int t = blockIdx.x * blockDim.x + threadIdx.x;
    int node = t >> 4;
    if (node >= NN) return;
    int sl = t & 15;
    const size_t lo = (size_t)sl * 8;

    int b = __ldg(&g_rowstart[node]), e = __ldg(&g_rowstart[node + 1]);
    float acc[8];
    #pragma unroll
    for (int i = 0; i < 8; i++) acc[i] = 0.f;

    int j = b;
    for (; j + 3 < e; j += 4) {
        int s0 = __ldg(&g_csrc[j]);
        int s1 = __ldg(&g_csrc[j + 1]);
        int s2 = __ldg(&g_csrc[j + 2]);
        int s3 = __ldg(&g_csrc[j + 3]);
        uint4 u0 = __ldg((const uint4*)(xin + (size_t)s0 * HD + lo));
        uint4 u1 = __ldg((const uint4*)(xin + (size_t)s1 * HD + lo));
        uint4 u2 = __ldg((const uint4*)(xin + (size_t)s2 * HD + lo));
        uint4 u3 = __ldg((const uint4*)(xin + (size_t)s3 * HD + lo));
        const u32* w0 = &u0.x; const u32* w1 = &u1.x;
        const u32* w2 = &u2.x; const u32* w3 = &u3.x;
        #pragma unroll
        for (int k = 0; k < 4; k++) {
            __half2 p0 = __hadd2(*(const __half2*)&w0[k], *(const __half2*)&w1[k]);
            __half2 p1 = __hadd2(*(const __half2*)&w2[k], *(const __half2*)&w3[k]);
            float2 f0 = __half22float2(p0);
            float2 f1 = __half22float2(p1);
            acc[2 * k]     += f0.x + f1.x;
            acc[2 * k + 1] += f0.y + f1.y;
        }
    }
    if (j + 1 < e) {
        int s0 = __ldg(&g_csrc[j]);
        int s1 = __ldg(&g_csrc[j + 1]);
        uint4 u0 = __ldg((const uint4*)(xin + (size_t)s0 * HD + lo));
        uint4 u1 = __ldg((const uint4*)(xin + (size_t)s1 * HD + lo));
        const u32* w0 = &u0.x; const u32* w1 = &u1.x;
        #pragma unroll
        for (int k = 0; k < 4; k++) {
            __half2 p0 = __hadd2(*(const __half2*)&w0[k], *(const __half2*)&w1[k]);
            float2 f0 = __half22float2(p0);
            acc[2 * k]     += f0.x;
            acc[2 * k + 1] += f0.y;
        }
        j += 2;
    }
    if (j < e) {
        int s0 = __ldg(&g_csrc[j]);
        uint4 u0 = __ldg((const uint4*)(xin + (size_t)s0 * HD + lo));
        const u32* w0 = &u0.x;
        #pragma unroll
        for (int k = 0; k < 4; k++) {
            float2 f0 = __half22float2(*(const __half2*)&w0[k]);
            acc[2 * k]     += f0.x;
            acc[2 * k + 1] += f0.y;
        }
    }

    float inv = 1.0f / fmaxf((float)(e - b), 1.0f);
    u32 ov[4];
    #pragma unroll
    for (int k = 0; k < 4; k++) {
        __half2 hv = __floats2half2_rn(acc[2 * k] * inv, acc[2 * k + 1] * inv);
        ov[k] = *(u32*)&hv;
    }
    uint4 o; o.x = ov[0]; o.y = ov[1]; o.z = ov[2]; o.w = ov[3];
    *(uint4*)(g_agg + (size_t)node * HD + lo) = o;
}

// ================= pipelined node GEMM: fp16 A and B, cp.async everything =====
// Block: 128 nodes, 256 threads = 8 warps (4 row x 2 col groups), warp tile 32 x N_/2.
// K = 256 as 4 chunks of 64 (agg,agg,x,x); A and B double-buffered cp.async.
// LAST=false: fp16 out (g_h) with BN+ReLU; LAST=true: fp32 out, bias only.
template<int N_, bool LAST>
__global__ __launch_bounds__(256, 2)
void k_node(const __half* __restrict__ xh, void* __restrict__ hout, int layer,
            const float* __restrict__ bl, const float* __restrict__ g,
            const float* __restrict__ be, const float* __restrict__ rm,
            const float* __restrict__ rv)
{
    extern __shared__ char smem[];
    constexpr int ABYT = 128 * KSB;          // one A buffer
    constexpr int BBYT = N_ * KSB;           // one B buffer
    constexpr int SM_B0 = 2 * ABYT;
    constexpr int SM_SC = 2 * ABYT + 2 * BBYT;
    constexpr int SM_SH = SM_SC + 512;
    constexpr int NJ = N_ / 16;

    const int tid  = threadIdx.x;
    const int wid  = tid >> 5;
    const int lane = tid & 31;
    const int wr   = (wid >> 1) * 32;
    const int wc   = (wid & 1) * (N_ / 2);
    const int nb   = blockIdx.x * 128;
    const u32 sb   = smem_u32(smem);

    // BN scale/shift (bias folded)
    if (tid < N_) {
        float s, sh;
        if (!LAST) {
            float sc_ = __ldg(&g[tid]) * rsqrtf(__ldg(&rv[tid]) + 1e-5f);
            s  = sc_;
            sh = (__ldg(&bl[tid]) - __ldg(&rm[tid])) * sc_ + __ldg(&be[tid]);
        } else {
            s  = 1.0f;
            sh = __ldg(&bl[tid]);
        }
        *(float*)(smem + SM_SC + tid * 4) = s;
        *(float*)(smem + SM_SH + tid * 4) = sh;
    }

    // ---- async stage of one chunk (A: 1024 x 16B, B: BBYT/16 x 16B) ----
    auto stage = [&](int cc, int buf) {
        const __half* asrc = (cc < 2) ? g_agg : xh;
        const int co = (cc & 1) * 128;       // byte offset within 256B row
        const u32 adst = sb + buf * ABYT;
        for (int idx = tid; idx < 1024; idx += 256) {
            int r = idx >> 3, i = idx & 7;
            cpasync16(adst + r * KSB + i * 16,
                      (const char*)(asrc + (size_t)(nb + r) * HD) + co + i * 16);
        }
        const char* bsrc = (const char*)&g_bimg[layer][cc][0];
        const u32 bdst = sb + SM_B0 + buf * BBYT;
        for (int i = tid; i < BBYT / 16; i += 256)
            cpasync16(bdst + i * 16, bsrc + i * 16);
    };

    stage(0, 0);
    CP_COMMIT();

    const u32 aOff = (u32)((wr + (lane & 15)) * KSB + (lane >> 4) * 16);
    const u32 bOff = (u32)((wc + (lane & 7)) * KSB + ((lane >> 3) & 1) * 16);

    float acc[2][NJ][4];
    #pragma unroll
    for (int m = 0; m < 2; m++)
        #pragma unroll
        for (int j = 0; j < NJ; j++) {
            acc[m][j][0] = 0.f; acc[m][j][1] = 0.f;
            acc[m][j][2] = 0.f; acc[m][j][3] = 0.f;
        }

    #pragma unroll
    for (int chunk = 0; chunk < 4; chunk++) {
        if (chunk < 3) {
            stage(chunk + 1, (chunk + 1) & 1);
            CP_COMMIT();
            asm volatile("cp.async.wait_group 1;" ::: "memory");
        } else {
            asm volatile("cp.async.wait_group 0;" ::: "memory");
        }
        __syncthreads();   // chunk's buffers visible to all threads

        const u32 abuf = sb + (chunk & 1) * ABYT + aOff;
        const u32 bbuf = sb + SM_B0 + (chunk & 1) * BBYT + bOff;
        #pragma unroll
        for (int k16 = 0; k16 < 4; k16++) {
            u32 a0[4], a1[4];
            ldsm4(a0, abuf + k16 * 32);
            ldsm4(a1, abuf + 16 * KSB + k16 * 32);
            #pragma unroll
            for (int j = 0; j < NJ; j++) {
                u32 bh[2];
                ldsm2(bh, bbuf + j * 8 * KSB + k16 * 32);
                mma16816(acc[0][j], a0, bh);
                mma16816(acc[1][j], a1, bh);
            }
        }
        __syncthreads();   // done reading before next-next stage overwrites
    }

    // ---- epilogue ----
    const int cb = (lane & 3) * 2;
    #pragma unroll
    for (int m = 0; m < 2; m++) {
        int n0 = nb + wr + m * 16 + (lane >> 2);
        int n1 = n0 + 8;
        #pragma unroll
        for (int j = 0; j < NJ; j++) {
            int c = wc + j * 8 + cb;
            float s0 = *(const float*)(smem + SM_SC + c * 4);
            float s1 = *(const float*)(smem + SM_SC + (c + 1) * 4);
            float h0 = *(const float*)(smem + SM_SH + c * 4);
            float h1 = *(const float*)(smem + SM_SH + (c + 1) * 4);
            #pragma unroll
            for (int hh = 0; hh < 2; hh++) {
                int n = (hh == 0) ? n0 : n1;
                if (n >= NN) continue;
                float vx = acc[m][j][hh * 2 + 0] * s0 + h0;
                float vy = acc[m][j][hh * 2 + 1] * s1 + h1;
                if (!LAST) {
                    vx = fmaxf(vx, 0.f);
                    vy = fmaxf(vy, 0.f);
                    __half2 hv = __floats2half2_rn(vx, vy);
                    *(u32*)((__half*)hout + (size_t)n * N_ + c) = *(u32*)&hv;
                } else {
                    float2 o; o.x = vx; o.y = vy;
                    *(float2*)((float*)hout + (size_t)n * N_ + c) = o;
                }
            }
        }
    }
}

// ================= launch =================
extern "C" void kernel_launch(void* const* d_in, const int* in_sizes, int n_in,
                              void* d_out, int out_size) {
    const float* x    = (const float*)d_in[0];
    const int*   ei   = (const int*)  d_in[1];
    const float* Wl1  = (const float*)d_in[2];
    const float* bl1  = (const float*)d_in[3];
    const float* Wr1  = (const float*)d_in[4];
    const float* g1   = (const float*)d_in[5];
    const float* be1  = (const float*)d_in[6];
    const float* rm1  = (const float*)d_in[7];
    const float* rv1  = (const float*)d_in[8];
    const float* Wl2  = (const float*)d_in[9];
    const float* bl2  = (const float*)d_in[10];
    const float* Wr2  = (const float*)d_in[11];
    const float* g2   = (const float*)d_in[12];
    const float* be2  = (const float*)d_in[13];
    const float* rm2  = (const float*)d_in[14];
    const float* rv2  = (const float*)d_in[15];
    const float* Wl3  = (const float*)d_in[16];
    const float* bl3  = (const float*)d_in[17];
    const float* Wr3  = (const float*)d_in[18];
    const int* src = ei;
    const int* dst = ei + EE;
    float* out = (float*)d_out;

    __half *xh_p, *h_p;
    cudaGetSymbolAddress((void**)&xh_p, g_xh);
    cudaGetSymbolAddress((void**)&h_p,  g_h);

    constexpr int SMEM12 = 2 * 128 * KSB + 2 * HD  * KSB + 1024;   // 74752
    constexpr int SMEM3  = 2 * 128 * KSB + 2 * OD3 * KSB + 1024;   // 56320
    cudaFuncSetAttribute(k_node<HD, false>, cudaFuncAttributeMaxDynamicSharedMemorySize, SMEM12);
    cudaFuncSetAttribute(k_node<OD3, true>, cudaFuncAttributeMaxDynamicSharedMemorySize, SMEM3);

    const int GB = (NN * 16 + 255) / 256;   // 16 lanes/node
    const int NB = (NN + 127) / 128;        // 782
    const int P1 = (EE + XN + 255) / 256;
    const int P2 = (EE + 3 * 4 * 64 * HD + 255) / 256;

    // fused pre-processing: (hist + xhalf) -> scan -> (slot + bpack)
    k_pre1<<<P1, 256>>>(dst, x);
    k_scan<<<1, 1024>>>();
    k_pre2<<<P2, 256>>>(src, dst, Wl1, Wr1, Wl2, Wr2, Wl3, Wr3);

    // layer 1
    k_gather<<<GB, 256>>>(xh_p);
    k_node<HD, false><<<NB, 256, SMEM12>>>(xh_p, h_p, 0, bl1, g1, be1, rm1, rv1);

    // layer 2 (in place safe: node reads only its own rows of g_h / g_agg)
    k_gather<<<GB, 256>>>(h_p);
    k_node<HD, false><<<NB, 256, SMEM12>>>(h_p, h_p, 1, bl2, g2, be2, rm2, rv2);

    // layer 3
    k_gather<<<GB, 256>>>(h_p);
    k_node<OD3, true><<<NB, 256, SMEM3>>>(h_p, out, 2, bl3, bl3, bl3, bl3, bl3);
}